// round 4
// baseline (speedup 1.0000x reference)
#include <cuda_runtime.h>
#include <cuda_bf16.h>
#include <cstdint>

#define H     512
#define SEQ   4096
#define R3    1536      // 3*H
#define NCTA  128       // persistent recurrence CTAs (<= 148 SMs -> one wave)

#define NGRP    128     // one 4-unit group per polling thread
#define GSTRIDE 2560    // bytes between groups -> spreads over ~150 L2 slices

// ---------------------------------------------------------------------------
// Device scratch (no allocations allowed anywhere)
// ---------------------------------------------------------------------------
__device__ float g_gx[SEQ * R3];                       // input-side projections (25 MB)
__device__ unsigned char g_hraw[2][NGRP * GSTRIDE];    // strided tagged h (640 KB)
__device__ float g_hT[H];                              // final hidden state

// pair (value, tag) for unit u in parity buffer par:
//   group g = u >> 2 at offset g*GSTRIDE, slot (u & 3) * 8 bytes
__device__ __forceinline__ float2* pair_ptr(int par, int u) {
    return (float2*)(g_hraw[par] + (size_t)(u >> 2) * GSTRIDE + (u & 3) * 8);
}

// ---------------------------------------------------------------------------
// Acquire/release helpers (GPU scope; L2 is the coherence point)
// ---------------------------------------------------------------------------
__device__ __forceinline__ float4 ld_acq_f4(const float2* p) {
    float4 v;
    asm volatile("ld.acquire.gpu.v4.f32 {%0,%1,%2,%3}, [%4];"
                 : "=f"(v.x), "=f"(v.y), "=f"(v.z), "=f"(v.w)
                 : "l"(p) : "memory");
    return v;
}
__device__ __forceinline__ void st_rel_b64(float2* p, float val, int tag) {
    unsigned long long pk = ((unsigned long long)(unsigned)tag << 32) |
                            (unsigned long long)__float_as_uint(val);
    asm volatile("st.release.gpu.b64 [%0], %1;" :: "l"(p), "l"(pk) : "memory");
}
__device__ __forceinline__ int tag_of(float f) { return __float_as_int(f); }

// ---------------------------------------------------------------------------
// Kernel 0: reset tags so graph replays never see stale tags from a prior run
// ---------------------------------------------------------------------------
__global__ void clear_kernel() {
    const int i = threadIdx.x;            // 0..1023 = par*512 + u
    if (i < 2 * H) {
        float2* p = pair_ptr(i >> 9, i & (H - 1));
        p->y = __int_as_float(-1);
    }
}

// ---------------------------------------------------------------------------
// Kernel 1: gx[t][r] = dot(emb[x[t]], w_ih[r]) + b_ih[r]
// 64x64 output tile per block, k-chunks of 16, 256 threads, 4x4 microtile.
// ---------------------------------------------------------------------------
__global__ void gx_kernel(const void* __restrict__ xr,
                          const float* __restrict__ emb,
                          const float* __restrict__ w_ih,
                          const float* __restrict__ b_ih) {
    __shared__ float As[16][68];
    __shared__ float Bs[16][68];

    const int t0  = blockIdx.x * 64;
    const int r0  = blockIdx.y * 64;
    const int tid = threadIdx.x;
    const int tl  = tid >> 2;
    const int kq  = tid & 3;
    const int tx  = tid & 15;
    const int ty  = tid >> 4;

    // int64 vs int32 index detection (JAX may silently downcast)
    const int*       x32 = (const int*)xr;
    const long long* x64 = (const long long*)xr;
    const bool is64 = (x32[1] == 0 && x32[3] == 0 && x32[5] == 0);
    const int xi = is64 ? (int)x64[t0 + tl] : x32[t0 + tl];

    const float* arow = emb  + (size_t)xi * H + kq * 4;
    const float* brow = w_ih + (size_t)(r0 + tl) * H + kq * 4;

    float acc[4][4];
#pragma unroll
    for (int i = 0; i < 4; i++)
#pragma unroll
        for (int j = 0; j < 4; j++) acc[i][j] = 0.f;

    for (int k0 = 0; k0 < H; k0 += 16) {
        float4 av = *(const float4*)(arow + k0);
        float4 bv = *(const float4*)(brow + k0);
        As[kq * 4 + 0][tl] = av.x; As[kq * 4 + 1][tl] = av.y;
        As[kq * 4 + 2][tl] = av.z; As[kq * 4 + 3][tl] = av.w;
        Bs[kq * 4 + 0][tl] = bv.x; Bs[kq * 4 + 1][tl] = bv.y;
        Bs[kq * 4 + 2][tl] = bv.z; Bs[kq * 4 + 3][tl] = bv.w;
        __syncthreads();
#pragma unroll
        for (int kk = 0; kk < 16; kk++) {
            float4 a = *(const float4*)&As[kk][ty * 4];
            float4 b = *(const float4*)&Bs[kk][tx * 4];
            acc[0][0] = fmaf(a.x, b.x, acc[0][0]); acc[0][1] = fmaf(a.x, b.y, acc[0][1]);
            acc[0][2] = fmaf(a.x, b.z, acc[0][2]); acc[0][3] = fmaf(a.x, b.w, acc[0][3]);
            acc[1][0] = fmaf(a.y, b.x, acc[1][0]); acc[1][1] = fmaf(a.y, b.y, acc[1][1]);
            acc[1][2] = fmaf(a.y, b.z, acc[1][2]); acc[1][3] = fmaf(a.y, b.w, acc[1][3]);
            acc[2][0] = fmaf(a.z, b.x, acc[2][0]); acc[2][1] = fmaf(a.z, b.y, acc[2][1]);
            acc[2][2] = fmaf(a.z, b.z, acc[2][2]); acc[2][3] = fmaf(a.z, b.w, acc[2][3]);
            acc[3][0] = fmaf(a.w, b.x, acc[3][0]); acc[3][1] = fmaf(a.w, b.y, acc[3][1]);
            acc[3][2] = fmaf(a.w, b.z, acc[3][2]); acc[3][3] = fmaf(a.w, b.w, acc[3][3]);
        }
        __syncthreads();
    }

#pragma unroll
    for (int i = 0; i < 4; i++) {
        const int t = t0 + ty * 4 + i;
#pragma unroll
        for (int j = 0; j < 4; j++) {
            const int r = r0 + tx * 4 + j;
            g_gx[(size_t)t * R3 + r] = acc[i][j] + b_ih[r];
        }
    }
}

// ---------------------------------------------------------------------------
// Kernel 2: persistent GRU recurrence, barrier-free tagged-value protocol.
// Tagged pairs are grouped 4-per-polling-thread (32B sector) and groups are
// strided 2560B apart so the 16K concurrent poll loads spread over ~150 L2
// slices instead of 8 (the R2 layout's slice serialization was the 3300
// cyc/step bottleneck).
// 128 CTAs x 128 threads; warp w owns unit u = blockIdx.x*4 + w with its
// 3x512 w_hh rows register-resident. Per step: 128 threads poll disjoint
// groups, stage values to smem, sync, compute from smem.
// Overwrite safety: a writer reaches parity buffer p at step t+2 only after
// observing ALL tags of step t+1, which requires every reader to have
// finished consuming buffer p at step t+1.
// ---------------------------------------------------------------------------
__global__ void __launch_bounds__(128, 1)
rec_kernel(const float* __restrict__ w_hh, const float* __restrict__ b_hh) {
    __shared__ float h_s[H];

    const int tid = threadIdx.x;
    const int w   = tid >> 5;
    const int l   = tid & 31;
    const int u   = blockIdx.x * 4 + w;        // hidden unit 0..511

    // 48 register-resident weights: k = 4*l + 128*i + c, gates r/z/n
    float wr[48];
#pragma unroll
    for (int g = 0; g < 3; g++) {
        const float* wp = w_hh + (size_t)(u + H * g) * H + 4 * l;
#pragma unroll
        for (int i = 0; i < 4; i++) {
            float4 v = *(const float4*)(wp + 128 * i);
            wr[g * 16 + i * 4 + 0] = v.x;
            wr[g * 16 + i * 4 + 1] = v.y;
            wr[g * 16 + i * 4 + 2] = v.z;
            wr[g * 16 + i * 4 + 3] = v.w;
        }
    }
    const float bhr = b_hh[u];
    const float bhz = b_hh[u + H];
    const float bhn = b_hh[u + 2 * H];

    float2* const wr_pair0 = pair_ptr(0, u);
    float2* const wr_pair1 = pair_ptr(1, u);

    for (int t = 0; t < SEQ; t++) {
        const int par = t & 1;

        // gx loads are independent of h -> issue before the poll
        const float* gxt = g_gx + (size_t)t * R3;
        const float pgr = __ldg(gxt + u);
        const float pgz = __ldg(gxt + H + u);
        const float pgn = __ldg(gxt + 2 * H + u);

        float a0 = 0.f, a1 = 0.f, a2 = 0.f;
        float hold = 0.f;

        if (t > 0) {
            // cooperative poll: thread tid owns the 4 units of group tid
            const float2* base =
                (const float2*)(g_hraw[par ^ 1] + (size_t)tid * GSTRIDE);
            const int exp_tag = t - 1;
            float4 c0, c1;
            for (;;) {
                c0 = ld_acq_f4(base);
                c1 = ld_acq_f4(base + 2);
                if ((tag_of(c0.y) == exp_tag) & (tag_of(c0.w) == exp_tag) &
                    (tag_of(c1.y) == exp_tag) & (tag_of(c1.w) == exp_tag)) break;
            }
            h_s[4 * tid + 0] = c0.x;
            h_s[4 * tid + 1] = c0.z;
            h_s[4 * tid + 2] = c1.x;
            h_s[4 * tid + 3] = c1.z;
            __syncthreads();

            hold = h_s[u];
#pragma unroll
            for (int i = 0; i < 4; i++) {
                const float4 h4 = *(const float4*)&h_s[4 * l + 128 * i];
                a0 = fmaf(wr[i * 4 + 0], h4.x, a0);
                a0 = fmaf(wr[i * 4 + 1], h4.y, a0);
                a0 = fmaf(wr[i * 4 + 2], h4.z, a0);
                a0 = fmaf(wr[i * 4 + 3], h4.w, a0);
                a1 = fmaf(wr[16 + i * 4 + 0], h4.x, a1);
                a1 = fmaf(wr[16 + i * 4 + 1], h4.y, a1);
                a1 = fmaf(wr[16 + i * 4 + 2], h4.z, a1);
                a1 = fmaf(wr[16 + i * 4 + 3], h4.w, a1);
                a2 = fmaf(wr[32 + i * 4 + 0], h4.x, a2);
                a2 = fmaf(wr[32 + i * 4 + 1], h4.y, a2);
                a2 = fmaf(wr[32 + i * 4 + 2], h4.z, a2);
                a2 = fmaf(wr[32 + i * 4 + 3], h4.w, a2);
            }
            // smem mirror is re-staged next step; everyone must be done reading
            __syncthreads();
        }

#pragma unroll
        for (int off = 16; off > 0; off >>= 1) {
            a0 += __shfl_xor_sync(0xffffffffu, a0, off);
            a1 += __shfl_xor_sync(0xffffffffu, a1, off);
            a2 += __shfl_xor_sync(0xffffffffu, a2, off);
        }

        if (l == 0) {
            const float r = 1.f / (1.f + __expf(-(pgr + a0 + bhr)));
            const float z = 1.f / (1.f + __expf(-(pgz + a1 + bhz)));
            const float e = __expf(2.f * (pgn + r * (a2 + bhn)));
            const float n = 1.f - 2.f / (e + 1.f);        // tanh, overflow-safe
            const float hnew = n + z * (hold - n);         // (1-z)*n + z*h
            st_rel_b64(par ? wr_pair1 : wr_pair0, hnew, t);
            if (t == SEQ - 1) g_hT[u] = hnew;
        }
    }
}

// ---------------------------------------------------------------------------
// Kernel 3: logit = dot(hT, dec_w) + dec_b; stable BCE-with-logits loss.
// ---------------------------------------------------------------------------
__global__ void loss_kernel(const float* __restrict__ target,
                            const float* __restrict__ dec_w,
                            const float* __restrict__ dec_b,
                            float* __restrict__ out) {
    __shared__ float red[8];
    const int tid = threadIdx.x;
    const int l = tid & 31, w = tid >> 5;
    float s = 0.f;
    for (int k = tid; k < H; k += 256) s += g_hT[k] * dec_w[k];
#pragma unroll
    for (int off = 16; off > 0; off >>= 1) s += __shfl_xor_sync(0xffffffffu, s, off);
    if (l == 0) red[w] = s;
    __syncthreads();
    if (tid == 0) {
        float tot = 0.f;
#pragma unroll
        for (int i = 0; i < 8; i++) tot += red[i];
        const float logit = tot + dec_b[0];
        const float tt = target[0];
        const float lse = log1pf(expf(-fabsf(logit)));     // shared term
        const float ls_p = fminf(logit, 0.f) - lse;        // log_sigmoid(logit)
        const float ls_m = fminf(-logit, 0.f) - lse;       // log_sigmoid(-logit)
        out[0] = -(tt * ls_p + (1.f - tt) * ls_m);
    }
}

// ---------------------------------------------------------------------------
// Launch
// ---------------------------------------------------------------------------
extern "C" void kernel_launch(void* const* d_in, const int* in_sizes, int n_in,
                              void* d_out, int out_size) {
    const void*  x      = d_in[0];
    const float* target = (const float*)d_in[1];
    const float* emb    = (const float*)d_in[2];
    const float* w_ih   = (const float*)d_in[3];
    const float* w_hh   = (const float*)d_in[4];
    const float* b_ih   = (const float*)d_in[5];
    const float* b_hh   = (const float*)d_in[6];
    const float* dec_w  = (const float*)d_in[7];
    const float* dec_b  = (const float*)d_in[8];

    clear_kernel<<<1, 1024>>>();
    dim3 g1(SEQ / 64, R3 / 64);
    gx_kernel<<<g1, 256>>>(x, emb, w_ih, b_ih);
    rec_kernel<<<NCTA, 128>>>(w_hh, b_hh);
    loss_kernel<<<1, 256>>>(target, dec_w, dec_b, (float*)d_out);
}

// round 11
// speedup vs baseline: 1.3536x; 1.3536x over previous
#include <cuda_runtime.h>
#include <cuda_bf16.h>
#include <cstdint>

#define H       512
#define SEQ     4096
#define R3      1536      // 3*H
#define CLUSTER 16        // single nonportable 16-CTA cluster runs the recurrence
#define NCTA_FB 128       // fallback: persistent poll CTAs (one wave)

// ---------------------------------------------------------------------------
// Device scratch (no allocations allowed anywhere)
// ---------------------------------------------------------------------------
__device__ float  g_gx[SEQ * R3];  // input projections; b_ih (+b_hh for r/z) folded in
__device__ float  g_hT[H];         // final hidden state
__device__ float2 g_h2[2][H];      // fallback path: double-buffered (value, tag)

// ---------------------------------------------------------------------------
// Packed dual-FMA (FFMA2): only reachable from PTX fma.rn.f32x2 on sm_103a
// ---------------------------------------------------------------------------
__device__ __forceinline__ float2 fma2(float2 a, float2 b, float2 c) {
    unsigned long long ra = *reinterpret_cast<unsigned long long*>(&a);
    unsigned long long rb = *reinterpret_cast<unsigned long long*>(&b);
    unsigned long long rc = *reinterpret_cast<unsigned long long*>(&c);
    unsigned long long rd;
    asm("fma.rn.f32x2 %0, %1, %2, %3;" : "=l"(rd) : "l"(ra), "l"(rb), "l"(rc));
    return *reinterpret_cast<float2*>(&rd);
}

// ---------------------------------------------------------------------------
// Acquire/release helpers for the fallback path (L2 is the coherence point)
// ---------------------------------------------------------------------------
__device__ __forceinline__ float4 ld_acq_f4(const float2* p) {
    float4 v;
    asm volatile("ld.acquire.gpu.v4.f32 {%0,%1,%2,%3}, [%4];"
                 : "=f"(v.x), "=f"(v.y), "=f"(v.z), "=f"(v.w)
                 : "l"(p) : "memory");
    return v;
}
__device__ __forceinline__ void st_rel_b64(float2* p, float val, int tag) {
    unsigned long long pk = ((unsigned long long)(unsigned)tag << 32) |
                            (unsigned long long)__float_as_uint(val);
    asm volatile("st.release.gpu.b64 [%0], %1;" :: "l"(p), "l"(pk) : "memory");
}
__device__ __forceinline__ int tag_of(float f) { return __float_as_int(f); }

// ---------------------------------------------------------------------------
// Kernel 0: reset fallback tags so graph replays never see stale tags
// ---------------------------------------------------------------------------
__global__ void clear_kernel() {
    float2* p = &g_h2[0][0];
    if (threadIdx.x < 2 * H) p[threadIdx.x].y = __int_as_float(-1);
}

// ---------------------------------------------------------------------------
// Kernel 1: gx[t][r] = dot(emb[x[t]], w_ih[r]) + b_ih[r] (+ b_hh[r] for the
// additive r/z gates; the n-gate's b_hh is multiplied by r, so it stays out).
// 64x64 output tile per block, k-chunks of 16, 256 threads, 4x4 microtile.
// ---------------------------------------------------------------------------
__global__ void gx_kernel(const void* __restrict__ xr,
                          const float* __restrict__ emb,
                          const float* __restrict__ w_ih,
                          const float* __restrict__ b_ih,
                          const float* __restrict__ b_hh) {
    __shared__ float As[16][68];
    __shared__ float Bs[16][68];

    const int t0  = blockIdx.x * 64;
    const int r0  = blockIdx.y * 64;
    const int tid = threadIdx.x;
    const int tl  = tid >> 2;
    const int kq  = tid & 3;
    const int tx  = tid & 15;
    const int ty  = tid >> 4;

    // int64 vs int32 index detection (JAX may silently downcast)
    const int*       x32 = (const int*)xr;
    const long long* x64 = (const long long*)xr;
    const bool is64 = (x32[1] == 0 && x32[3] == 0 && x32[5] == 0);
    const int xi = is64 ? (int)x64[t0 + tl] : x32[t0 + tl];

    const float* arow = emb  + (size_t)xi * H + kq * 4;
    const float* brow = w_ih + (size_t)(r0 + tl) * H + kq * 4;

    float acc[4][4];
#pragma unroll
    for (int i = 0; i < 4; i++)
#pragma unroll
        for (int j = 0; j < 4; j++) acc[i][j] = 0.f;

    for (int k0 = 0; k0 < H; k0 += 16) {
        float4 av = *(const float4*)(arow + k0);
        float4 bv = *(const float4*)(brow + k0);
        As[kq * 4 + 0][tl] = av.x; As[kq * 4 + 1][tl] = av.y;
        As[kq * 4 + 2][tl] = av.z; As[kq * 4 + 3][tl] = av.w;
        Bs[kq * 4 + 0][tl] = bv.x; Bs[kq * 4 + 1][tl] = bv.y;
        Bs[kq * 4 + 2][tl] = bv.z; Bs[kq * 4 + 3][tl] = bv.w;
        __syncthreads();
#pragma unroll
        for (int kk = 0; kk < 16; kk++) {
            float4 a = *(const float4*)&As[kk][ty * 4];
            float4 b = *(const float4*)&Bs[kk][tx * 4];
            acc[0][0] = fmaf(a.x, b.x, acc[0][0]); acc[0][1] = fmaf(a.x, b.y, acc[0][1]);
            acc[0][2] = fmaf(a.x, b.z, acc[0][2]); acc[0][3] = fmaf(a.x, b.w, acc[0][3]);
            acc[1][0] = fmaf(a.y, b.x, acc[1][0]); acc[1][1] = fmaf(a.y, b.y, acc[1][1]);
            acc[1][2] = fmaf(a.y, b.z, acc[1][2]); acc[1][3] = fmaf(a.y, b.w, acc[1][3]);
            acc[2][0] = fmaf(a.z, b.x, acc[2][0]); acc[2][1] = fmaf(a.z, b.y, acc[2][1]);
            acc[2][2] = fmaf(a.z, b.z, acc[2][2]); acc[2][3] = fmaf(a.z, b.w, acc[2][3]);
            acc[3][0] = fmaf(a.w, b.x, acc[3][0]); acc[3][1] = fmaf(a.w, b.y, acc[3][1]);
            acc[3][2] = fmaf(a.w, b.z, acc[3][2]); acc[3][3] = fmaf(a.w, b.w, acc[3][3]);
        }
        __syncthreads();
    }

#pragma unroll
    for (int i = 0; i < 4; i++) {
        const int t = t0 + ty * 4 + i;
#pragma unroll
        for (int j = 0; j < 4; j++) {
            const int r = r0 + tx * 4 + j;
            float bias = b_ih[r] + (r < 2 * H ? b_hh[r] : 0.f);
            g_gx[(size_t)t * R3 + r] = acc[i][j] + bias;
        }
    }
}

// ---------------------------------------------------------------------------
// Kernel 2 (primary): GRU recurrence in ONE 16-CTA cluster, DSMEM exchange,
// SPLIT cluster barrier: per step, prefetch gx -> wait(prev) -> compute ->
// publish -> arrive. The gx L2 latency hides under the barrier wait, and the
// publish's DSMEM flight overlaps the next step's front end.
// Hazard proof (both directions):
//  * buf[p=t&1] written at t, read at t+1, re-written at t+2. Writer at t+2
//    passes wait(t+1) first; every reader's loads at t+1 precede its
//    arrive(t+1) -> reads done before re-write.
//  * A writer of buf[p] at t cannot race readers at t-1 (reading h[t-2] from
//    the same parity): it passed wait(t-1), which consumes every CTA's
//    arrive(t-1), which follows those reads in program order.
// Trailing wait consumes the final arrive before exit.
// ---------------------------------------------------------------------------
__global__ void __launch_bounds__(512, 1)
rec_kernel(const float* __restrict__ w_hh, const float* __restrict__ b_hh) {
    __shared__ float h_s[2][H];

    const int tid  = threadIdx.x;
    const int w    = tid >> 5;
    const int l    = tid & 31;
    const int half = l >> 4;
    const int sl   = l & 15;
    unsigned rank;
    asm("mov.u32 %0, %%cluster_ctarank;" : "=r"(rank));
    const int u = (int)rank * 32 + w * 2 + half;   // hidden unit 0..511

    // gate g, chunk i covers elems 4*sl + 64*i + 0..3 (96 weights as 48 f32x2)
    float2 wt[24][2];
#pragma unroll
    for (int g = 0; g < 3; g++)
#pragma unroll
        for (int i = 0; i < 8; i++) {
            float4 v = *(const float4*)(w_hh + (size_t)(u + H * g) * H + 4 * sl + 64 * i);
            wt[g * 8 + i][0] = make_float2(v.x, v.y);
            wt[g * 8 + i][1] = make_float2(v.z, v.w);
        }
    const float bhn = b_hh[u + 2 * H];   // only the n-gate bias survives the fold

    uint32_t hs0;
    asm("{ .reg .u64 t0; cvta.to.shared.u64 t0, %1; cvt.u32.u64 %0, t0; }"
        : "=r"(hs0) : "l"(&h_s[0][0]));

    float hlast = 0.f;
    for (int t = 0; t < SEQ; t++) {
        const int par = t & 1;

        // gx prefetch issues BEFORE the barrier wait; latency hides under it
        const float* gxt = g_gx + (size_t)t * R3 + u;
        const float pg0 = __ldg(gxt);
        const float pg1 = __ldg(gxt + H);
        const float pg2 = __ldg(gxt + 2 * H);

        if (t)  // consume the arrive from step t-1; makes h[t-1] visible
            asm volatile("barrier.cluster.wait.aligned;" ::: "memory");

        float2 A0 = make_float2(0.f, 0.f), A1 = A0, A2 = A0;
        float hold = 0.f;
        if (t) {
            const float* hb = h_s[par ^ 1];
            hold = hb[u];
#pragma unroll
            for (int i = 0; i < 8; i++) {
                float4 h4 = *(const float4*)(hb + 4 * sl + 64 * i);
                float2 ha = make_float2(h4.x, h4.y);
                float2 hc = make_float2(h4.z, h4.w);
                A0 = fma2(wt[i][0],      ha, A0); A0 = fma2(wt[i][1],      hc, A0);
                A1 = fma2(wt[8 + i][0],  ha, A1); A1 = fma2(wt[8 + i][1],  hc, A1);
                A2 = fma2(wt[16 + i][0], ha, A2); A2 = fma2(wt[16 + i][1], hc, A2);
            }
        }
        float a0 = A0.x + A0.y, a1 = A1.x + A1.y, a2 = A2.x + A2.y;
#pragma unroll
        for (int off = 8; off; off >>= 1) {       // butterfly within 16-lane group
            a0 += __shfl_xor_sync(0xffffffffu, a0, off);
            a1 += __shfl_xor_sync(0xffffffffu, a1, off);
            a2 += __shfl_xor_sync(0xffffffffu, a2, off);
        }

        // gates (redundant across the 16 lanes of the group)
        const float r = 1.f / (1.f + __expf(-(pg0 + a0)));
        const float z = 1.f / (1.f + __expf(-(pg1 + a1)));
        const float e = __expf(2.f * (pg2 + r * (a2 + bhn)));
        const float n = 1.f - 2.f / (e + 1.f);     // tanh, overflow-safe
        const float hnew = n + z * (hold - n);     // (1-z)*n + z*h
        hlast = hnew;

        // publish: lane sl delivers this unit's value to cluster CTA rank sl
        uint32_t laddr = hs0 + (uint32_t)(par * H + u) * 4u;
        asm volatile(
            "{ .reg .u32 ra; mapa.shared::cluster.u32 ra, %0, %1; "
            "st.shared::cluster.f32 [ra], %2; }"
            :: "r"(laddr), "r"((unsigned)sl), "f"(hnew) : "memory");

        // release-arrive: orders the DSMEM store; completion checked at t+1
        asm volatile("barrier.cluster.arrive.aligned;" ::: "memory");
    }
    if (sl == 0) g_hT[u] = hlast;
    // consume the final phase so no CTA exits with a peer's store in flight
    asm volatile("barrier.cluster.wait.aligned;" ::: "memory");
}

// ---------------------------------------------------------------------------
// Kernel 2 (fallback): R3's proven tagged-value poll design (passed @7551us),
// gate math adapted to the folded-bias gx. Used only if the cluster config is
// reported unsupported by the occupancy query.
// ---------------------------------------------------------------------------
__global__ void __launch_bounds__(128, 1)
rec_fallback(const float* __restrict__ w_hh, const float* __restrict__ b_hh) {
    __shared__ float h_s[H];

    const int tid = threadIdx.x;
    const int w   = tid >> 5;
    const int l   = tid & 31;
    const int u   = blockIdx.x * 4 + w;

    float wr[48];
#pragma unroll
    for (int g = 0; g < 3; g++) {
        const float* wp = w_hh + (size_t)(u + H * g) * H + 4 * l;
#pragma unroll
        for (int i = 0; i < 4; i++) {
            float4 v = *(const float4*)(wp + 128 * i);
            wr[g * 16 + i * 4 + 0] = v.x;
            wr[g * 16 + i * 4 + 1] = v.y;
            wr[g * 16 + i * 4 + 2] = v.z;
            wr[g * 16 + i * 4 + 3] = v.w;
        }
    }
    const float bhn = b_hh[u + 2 * H];

    for (int t = 0; t < SEQ; t++) {
        const int par = t & 1;

        const float* gxt = g_gx + (size_t)t * R3;
        const float pg0 = __ldg(gxt + u);
        const float pg1 = __ldg(gxt + H + u);
        const float pg2 = __ldg(gxt + 2 * H + u);

        float a0 = 0.f, a1 = 0.f, a2 = 0.f;
        float hold = 0.f;

        if (t > 0) {
            const float2* base = g_h2[par ^ 1] + 4 * tid;
            const int exp_tag = t - 1;
            float4 c0, c1;
            for (;;) {
                c0 = ld_acq_f4(base);
                c1 = ld_acq_f4(base + 2);
                if ((tag_of(c0.y) == exp_tag) & (tag_of(c0.w) == exp_tag) &
                    (tag_of(c1.y) == exp_tag) & (tag_of(c1.w) == exp_tag)) break;
            }
            h_s[4 * tid + 0] = c0.x;
            h_s[4 * tid + 1] = c0.z;
            h_s[4 * tid + 2] = c1.x;
            h_s[4 * tid + 3] = c1.z;
            __syncthreads();

            hold = h_s[u];
#pragma unroll
            for (int i = 0; i < 4; i++) {
                const float4 h4 = *(const float4*)&h_s[4 * l + 128 * i];
                a0 = fmaf(wr[i*4+0], h4.x, a0); a0 = fmaf(wr[i*4+1], h4.y, a0);
                a0 = fmaf(wr[i*4+2], h4.z, a0); a0 = fmaf(wr[i*4+3], h4.w, a0);
                a1 = fmaf(wr[16+i*4+0], h4.x, a1); a1 = fmaf(wr[16+i*4+1], h4.y, a1);
                a1 = fmaf(wr[16+i*4+2], h4.z, a1); a1 = fmaf(wr[16+i*4+3], h4.w, a1);
                a2 = fmaf(wr[32+i*4+0], h4.x, a2); a2 = fmaf(wr[32+i*4+1], h4.y, a2);
                a2 = fmaf(wr[32+i*4+2], h4.z, a2); a2 = fmaf(wr[32+i*4+3], h4.w, a2);
            }
            __syncthreads();
        }

#pragma unroll
        for (int off = 16; off > 0; off >>= 1) {
            a0 += __shfl_xor_sync(0xffffffffu, a0, off);
            a1 += __shfl_xor_sync(0xffffffffu, a1, off);
            a2 += __shfl_xor_sync(0xffffffffu, a2, off);
        }

        if (l == 0) {
            const float r = 1.f / (1.f + __expf(-(pg0 + a0)));
            const float z = 1.f / (1.f + __expf(-(pg1 + a1)));
            const float e = __expf(2.f * (pg2 + r * (a2 + bhn)));
            const float n = 1.f - 2.f / (e + 1.f);
            const float hnew = n + z * (hold - n);
            st_rel_b64(&g_h2[par][u], hnew, t);
            if (t == SEQ - 1) g_hT[u] = hnew;
        }
    }
}

// ---------------------------------------------------------------------------
// Kernel 3: logit = dot(hT, dec_w) + dec_b; stable BCE-with-logits loss.
// ---------------------------------------------------------------------------
__global__ void loss_kernel(const float* __restrict__ target,
                            const float* __restrict__ dec_w,
                            const float* __restrict__ dec_b,
                            float* __restrict__ out) {
    __shared__ float red[8];
    const int tid = threadIdx.x;
    const int l = tid & 31, w = tid >> 5;
    float s = 0.f;
    for (int k = tid; k < H; k += 256) s += g_hT[k] * dec_w[k];
#pragma unroll
    for (int off = 16; off > 0; off >>= 1) s += __shfl_xor_sync(0xffffffffu, s, off);
    if (l == 0) red[w] = s;
    __syncthreads();
    if (tid == 0) {
        float tot = 0.f;
#pragma unroll
        for (int i = 0; i < 8; i++) tot += red[i];
        const float logit = tot + dec_b[0];
        const float tt = target[0];
        const float lse = log1pf(expf(-fabsf(logit)));
        const float ls_p = fminf(logit, 0.f) - lse;
        const float ls_m = fminf(-logit, 0.f) - lse;
        out[0] = -(tt * ls_p + (1.f - tt) * ls_m);
    }
}

// ---------------------------------------------------------------------------
// Launch: deterministic dispatch — cluster path if the HW/driver accepts the
// 16-CTA nonportable cluster config, else the proven poll fallback.
// ---------------------------------------------------------------------------
extern "C" void kernel_launch(void* const* d_in, const int* in_sizes, int n_in,
                              void* d_out, int out_size) {
    const void*  x      = d_in[0];
    const float* target = (const float*)d_in[1];
    const float* emb    = (const float*)d_in[2];
    const float* w_ih   = (const float*)d_in[3];
    const float* w_hh   = (const float*)d_in[4];
    const float* b_ih   = (const float*)d_in[5];
    const float* b_hh   = (const float*)d_in[6];
    const float* dec_w  = (const float*)d_in[7];
    const float* dec_b  = (const float*)d_in[8];

    clear_kernel<<<1, 1024>>>();
    dim3 g1(SEQ / 64, R3 / 64);
    gx_kernel<<<g1, 256>>>(x, emb, w_ih, b_ih, b_hh);

    // capture-safe feasibility probe (pure query, not a stream op)
    cudaFuncSetAttribute(rec_kernel,
                         cudaFuncAttributeNonPortableClusterSizeAllowed, 1);
    cudaLaunchConfig_t cfg = {};
    cfg.gridDim  = dim3(CLUSTER, 1, 1);
    cfg.blockDim = dim3(512, 1, 1);
    cfg.dynamicSmemBytes = 0;
    cfg.stream = 0;
    cudaLaunchAttribute attrs[1];
    attrs[0].id = cudaLaunchAttributeClusterDimension;
    attrs[0].val.clusterDim.x = CLUSTER;
    attrs[0].val.clusterDim.y = 1;
    attrs[0].val.clusterDim.z = 1;
    cfg.attrs = attrs;
    cfg.numAttrs = 1;

    int nclusters = 0;
    cudaError_t q = cudaOccupancyMaxActiveClusters(&nclusters, rec_kernel, &cfg);

    if (q == cudaSuccess && nclusters >= 1) {
        cudaLaunchKernelEx(&cfg, rec_kernel, w_hh, b_hh);
    } else {
        rec_fallback<<<NCTA_FB, 128>>>(w_hh, b_hh);
    }

    loss_kernel<<<1, 256>>>(target, dec_w, dec_b, (float*)d_out);
}